// round 10
// baseline (speedup 1.0000x reference)
#include <cuda_runtime.h>
#include <cuda_fp16.h>
#include <math.h>
#include <stdint.h>

#define Bz   256
#define Pz   196
#define Hz   1024
#define Az   512
#define MBIG (Bz * Pz)   // 50176 = 392 * 128
#define HALF_ELEMS ((size_t)MBIG * Hz / 2)

// ------------------------------------------------------------------
// device scratch (allocations forbidden)
// ------------------------------------------------------------------
__device__ float  g_sent_aff[Bz * Hz];
__device__ float  g_hid_aff [Bz * Hz];
__device__ float  g_sent_att[Bz * Az];
__device__ float  g_hid_att [Bz * Az];
__device__ float  g_alpha_part[4 * MBIG];
__device__ float  g_ctx     [Bz * Hz];
__device__ float  g_aff_part[2 * 8 * Bz * Hz];  // [hid | sent] split-K=8 slabs
__device__ float  g_att_part[2 * 8 * Bz * Az];
__device__ float  g_fin_part[8 * Bz * Hz];
__device__ __half g_Ah[(size_t)MBIG * Hz];      // spatial fp16 (103 MB)
__device__ __half g_Bh[Hz * Az];                // W_v_att fp16 [K][N]

// ------------------------------------------------------------------
__device__ __forceinline__ uint32_t smem_u32(const void* p) {
    uint32_t a;
    asm("{ .reg .u64 t; cvta.to.shared.u64 t, %1; cvt.u32.u64 %0, t; }"
        : "=r"(a) : "l"(p));
    return a;
}
__device__ __forceinline__ void cpa16(uint32_t dst, const void* src) {
    asm volatile("cp.async.cg.shared.global [%0], [%1], 16;"
                 :: "r"(dst), "l"(src) : "memory");
}
#define CP_COMMIT() asm volatile("cp.async.commit_group;" ::: "memory")
#define CP_WAIT(n)  asm volatile("cp.async.wait_group %0;" :: "n"(n) : "memory")

__device__ __forceinline__ void ldsm_x4(uint32_t* r, uint32_t addr) {
    asm volatile("ldmatrix.sync.aligned.m8n8.x4.shared.b16 {%0,%1,%2,%3}, [%4];"
                 : "=r"(r[0]), "=r"(r[1]), "=r"(r[2]), "=r"(r[3]) : "r"(addr));
}
__device__ __forceinline__ void ldsm_x4_t(uint32_t* r, uint32_t addr) {
    asm volatile("ldmatrix.sync.aligned.m8n8.x4.trans.shared.b16 {%0,%1,%2,%3}, [%4];"
                 : "=r"(r[0]), "=r"(r[1]), "=r"(r[2]), "=r"(r[3]) : "r"(addr));
}
__device__ __forceinline__ void mma16816(float* c, const uint32_t* a, const uint32_t* b) {
    asm volatile(
        "mma.sync.aligned.m16n8k16.row.col.f32.f16.f16.f32 "
        "{%0,%1,%2,%3}, {%4,%5,%6,%7}, {%8,%9}, {%0,%1,%2,%3};"
        : "+f"(c[0]), "+f"(c[1]), "+f"(c[2]), "+f"(c[3])
        : "r"(a[0]), "r"(a[1]), "r"(a[2]), "r"(a[3]), "r"(b[0]), "r"(b[1]));
}

// MUFU-free reciprocal: bit-trick seed + 3 Newton steps (exact to fp32)
__device__ __forceinline__ float fastrcp(float q) {
    float r = __int_as_float(0x7EF311C3 - __float_as_int(q));
    r = r * (2.0f - q * r);
    r = r * (2.0f - q * r);
    r = r * (2.0f - q * r);
    return r;
}
// Eigen-style rational fast tanh (13/6), FMA-only, ~1e-6 abs error
__device__ __forceinline__ float fast_tanh(float x) {
    x = fminf(fmaxf(x, -7.90531110763549805f), 7.90531110763549805f);
    float x2 = x * x;
    float p = fmaf(x2, -2.76076847742355e-16f, 2.00018790482477e-13f);
    p = fmaf(x2, p, -8.60467152213735e-11f);
    p = fmaf(x2, p,  5.12229709037114e-08f);
    p = fmaf(x2, p,  1.48572235717979e-05f);
    p = fmaf(x2, p,  6.37261928875436e-04f);
    p = fmaf(x2, p,  4.89352455891786e-03f);
    p = x * p;
    float q = fmaf(x2, 1.19825839466702e-06f, 1.18534705686654e-04f);
    q = fmaf(x2, q, 2.26843463243900e-03f);
    q = fmaf(x2, q, 4.89352518554385e-03f);
    return p * fastrcp(q);
}

// ------------------------------------------------------------------
// fp32 -> fp16 conversions (streaming, full MLP); offset for split launch
// ------------------------------------------------------------------
__global__ void convA_kernel(const float* __restrict__ Sp, size_t off) {
    size_t base = off + ((size_t)blockIdx.x * 256 + threadIdx.x) * 8;
    float4 x0 = *(const float4*)&Sp[base];
    float4 x1 = *(const float4*)&Sp[base + 4];
    __half2 h[4];
    h[0] = __floats2half2_rn(x0.x, x0.y);
    h[1] = __floats2half2_rn(x0.z, x0.w);
    h[2] = __floats2half2_rn(x1.x, x1.y);
    h[3] = __floats2half2_rn(x1.z, x1.w);
    *(uint4*)&g_Ah[base] = *(uint4*)h;
}
__global__ void convB_kernel(const float* __restrict__ Wv) {
    size_t base = ((size_t)blockIdx.x * 256 + threadIdx.x) * 8;
    float4 x0 = *(const float4*)&Wv[base];
    float4 x1 = *(const float4*)&Wv[base + 4];
    __half2 h[4];
    h[0] = __floats2half2_rn(x0.x, x0.y);
    h[1] = __floats2half2_rn(x0.z, x0.w);
    h[2] = __floats2half2_rn(x1.x, x1.y);
    h[3] = __floats2half2_rn(x1.z, x1.w);
    *(uint4*)&g_Bh[base] = *(uint4*)h;
}

// ------------------------------------------------------------------
// big fused attention GEMM on HMMA, BM=128 BN=128 BK=32
// 3-stage cp.async ring. grid (4 chunks, m-tiles), m_base for split launch.
// Epilogue tanh is FMA-only (fast_tanh) -> MUFU no longer the bottleneck.
// ------------------------------------------------------------------
#define AS_STRIDE 80
#define BS_STRIDE 272
#define AS_BYTES  10240
#define BS_BYTES  8704
#define STG_BYTES (AS_BYTES + BS_BYTES)
#define NSTAGE    3

__global__ void __launch_bounds__(256, 2)
big_attn_mma(const float* __restrict__ bv,   // (512)
             const float* __restrict__ Wa,   // (512)
             int m_base)
{
    extern __shared__ char dyn[];
    __shared__ float red[128 * 4];

    const int tid  = threadIdx.x;
    const int wid  = tid >> 5;
    const int lane = tid & 31;
    const int wm   = wid & 1;
    const int wn   = wid >> 1;
    const int m0   = m_base + blockIdx.y * 128;
    const int n0g  = blockIdx.x * 128;

    const uint32_t dyn_s = smem_u32(dyn);

    float acc[4][4][4] = {};

    auto prefetch = [&](int kc, int s) {
        const uint32_t as = dyn_s + s * STG_BYTES;
        const uint32_t bs = as + AS_BYTES;
        const int k0 = kc * 32;
#pragma unroll
        for (int g = 0; g < 2; g++) {
            int idx = g * 256 + tid;
            int row = idx >> 2, c = idx & 3;
            cpa16(as + row * AS_STRIDE + c * 16,
                  &g_Ah[(size_t)(m0 + row) * 1024 + k0 + c * 8]);
        }
#pragma unroll
        for (int g = 0; g < 2; g++) {
            int idx = g * 256 + tid;
            int row = idx >> 4, c = idx & 15;
            cpa16(bs + row * BS_STRIDE + c * 16,
                  &g_Bh[(size_t)(k0 + row) * 512 + n0g + c * 8]);
        }
        CP_COMMIT();
    };

    prefetch(0, 0);
    prefetch(1, 1);

    int stage = 0;
    for (int kc = 0; kc < 32; kc++) {
        if (kc < 31) { CP_WAIT(1); } else { CP_WAIT(0); }
        __syncthreads();

        if (kc < 30) {
            int ps = stage + 2; if (ps >= NSTAGE) ps -= NSTAGE;
            prefetch(kc + 2, ps);
        }

        const uint32_t as = dyn_s + stage * STG_BYTES;
        const uint32_t bs = as + AS_BYTES;

#pragma unroll
        for (int k16 = 0; k16 < 2; k16++) {
            uint32_t a_frag[4][4];
            uint32_t b_frag[4][2];
#pragma unroll
            for (int mt = 0; mt < 4; mt++) {
                int row = wm * 64 + mt * 16 + (lane & 15);
                int col = k16 * 16 + ((lane >> 4) << 3);
                ldsm_x4(a_frag[mt], as + row * AS_STRIDE + col * 2);
            }
#pragma unroll
            for (int p = 0; p < 2; p++) {
                int krow = k16 * 16 + ((lane >> 3) & 1) * 8 + (lane & 7);
                int col  = wn * 32 + p * 16 + ((lane >> 4) << 3);
                uint32_t r[4];
                ldsm_x4_t(r, bs + krow * BS_STRIDE + col * 2);
                b_frag[2 * p][0] = r[0]; b_frag[2 * p][1] = r[1];
                b_frag[2 * p + 1][0] = r[2]; b_frag[2 * p + 1][1] = r[3];
            }
#pragma unroll
            for (int mt = 0; mt < 4; mt++)
#pragma unroll
                for (int nt = 0; nt < 4; nt++)
                    mma16816(acc[mt][nt], a_frag[mt], b_frag[nt]);
        }
        stage++; if (stage >= NSTAGE) stage = 0;
    }
    __syncthreads();

    // ---- epilogue: alpha_part[m] = sum_n fast_tanh(D + bv + hid_att) * Wa ----
    const int lane4 = lane & 3, laned4 = lane >> 2;
    float bvv[8], waa[8];
#pragma unroll
    for (int nt = 0; nt < 4; nt++) {
        int ng = n0g + wn * 32 + nt * 8 + lane4 * 2;
        bvv[2 * nt] = bv[ng];     bvv[2 * nt + 1] = bv[ng + 1];
        waa[2 * nt] = Wa[ng];     waa[2 * nt + 1] = Wa[ng + 1];
    }
#pragma unroll
    for (int mt = 0; mt < 4; mt++) {
        float srow[2] = {0.f, 0.f};
#pragma unroll
        for (int h = 0; h < 2; h++) {
            int rloc = wm * 64 + mt * 16 + laned4 + h * 8;
            int bb = (m0 + rloc) / Pz;
            const float* ha = &g_hid_att[(size_t)bb * Az + n0g];
#pragma unroll
            for (int nt = 0; nt < 4; nt++) {
                int cl = wn * 32 + nt * 8 + lane4 * 2;
                float z0 = acc[mt][nt][2 * h]     + bvv[2 * nt]     + ha[cl];
                float z1 = acc[mt][nt][2 * h + 1] + bvv[2 * nt + 1] + ha[cl + 1];
                srow[h] += fast_tanh(z0) * waa[2 * nt]
                         + fast_tanh(z1) * waa[2 * nt + 1];
            }
        }
#pragma unroll
        for (int h = 0; h < 2; h++) {
            float s = srow[h];
            s += __shfl_xor_sync(0xffffffffu, s, 1);
            s += __shfl_xor_sync(0xffffffffu, s, 2);
            if (lane4 == 0) {
                int rloc = wm * 64 + mt * 16 + laned4 + h * 8;
                red[rloc * 4 + wn] = s;
            }
        }
    }
    __syncthreads();
    if (tid < 128) {
        float s = red[tid * 4] + red[tid * 4 + 1] + red[tid * 4 + 2] + red[tid * 4 + 3];
        g_alpha_part[(size_t)blockIdx.x * MBIG + m0 + tid] = s;
    }
}

// ------------------------------------------------------------------
// split-K=8 fp32 GEMM, single job per launch (z = 8 K-splits)
// ------------------------------------------------------------------
__global__ void gemm_splitk(const float* __restrict__ A,
                            const float* __restrict__ W,
                            float* __restrict__ part, int N)
{
    __shared__ __align__(16) float As[16][68];
    __shared__ __align__(16) float Bs[16][68];
    const int ks = blockIdx.z;
    const int tid = threadIdx.x;
    const int tx = tid & 15, ty = tid >> 4;
    const int m0 = blockIdx.y * 64, n0 = blockIdx.x * 64;
    const int kbase = ks * 128;

    const int arow = tid >> 2, acg = (tid & 3) * 4;
    const int brow = tid >> 4, bcol = (tid & 15) * 4;

    float acc[4][4] = {};

    for (int k0 = kbase; k0 < kbase + 128; k0 += 16) {
        float4 av = *(const float4*)&A[(size_t)(m0 + arow) * 1024 + k0 + acg];
        As[acg + 0][arow] = av.x; As[acg + 1][arow] = av.y;
        As[acg + 2][arow] = av.z; As[acg + 3][arow] = av.w;
        *(float4*)&Bs[brow][bcol] =
            *(const float4*)&W[(size_t)(k0 + brow) * N + n0 + bcol];
        __syncthreads();
#pragma unroll
        for (int k = 0; k < 16; k++) {
            float4 a4 = *(const float4*)&As[k][ty * 4];
            float4 b4 = *(const float4*)&Bs[k][tx * 4];
            float a[4] = {a4.x, a4.y, a4.z, a4.w};
            float b[4] = {b4.x, b4.y, b4.z, b4.w};
#pragma unroll
            for (int i = 0; i < 4; i++)
#pragma unroll
                for (int j = 0; j < 4; j++) acc[i][j] += a[i] * b[j];
        }
        __syncthreads();
    }

    float* out = part + (size_t)ks * 256 * N;
#pragma unroll
    for (int i = 0; i < 4; i++) {
        int m = m0 + ty * 4 + i;
#pragma unroll
        for (int j = 0; j < 4; j++)
            out[(size_t)m * N + n0 + tx * 4 + j] = acc[i][j];
    }
}

// combine 8 split-K partials + bias + activation (0=none,1=relu,2=tanh)
__global__ void combine1(const float* __restrict__ part,
                         const float* __restrict__ bias,
                         float* __restrict__ o, int N, int act)
{
    const size_t e = ((size_t)blockIdx.x * 256 + threadIdx.x) * 4;
    const size_t slab = (size_t)256 * N;
    float4 s = *(const float4*)(part + e);
#pragma unroll
    for (int t = 1; t < 8; t++) {
        float4 q = *(const float4*)(part + t * slab + e);
        s.x += q.x; s.y += q.y; s.z += q.z; s.w += q.w;
    }
    const int n = (int)(e & (size_t)(N - 1));
    float4 bvec = *(const float4*)&bias[n];
    s.x += bvec.x; s.y += bvec.y; s.z += bvec.z; s.w += bvec.w;
    if (act == 1) {
        s.x = fmaxf(s.x, 0.f); s.y = fmaxf(s.y, 0.f);
        s.z = fmaxf(s.z, 0.f); s.w = fmaxf(s.w, 0.f);
    } else if (act == 2) {
        s.x = tanhf(s.x); s.y = tanhf(s.y); s.z = tanhf(s.z); s.w = tanhf(s.w);
    }
    *(float4*)(o + e) = s;
}

// ------------------------------------------------------------------
// merged softmax (197 logits incl. sentinel) + context per batch
// context reads fp16 g_Ah (half the traffic of fp32 spatial)
// ------------------------------------------------------------------
__global__ void softmax_context_kernel(const float* __restrict__ Wa,
                                       float* __restrict__ out_w,
                                       float* __restrict__ out_beta)
{
    const int b = blockIdx.x;
    const int tid = threadIdx.x;
    __shared__ float sh[256];
    __shared__ float vals[197];
    __shared__ float ws[197];

    float s = 0.f;
    for (int a = tid; a < 512; a += 256)
        s += tanhf(g_sent_att[b * 512 + a] + g_hid_att[b * 512 + a]) * Wa[a];
    sh[tid] = s; __syncthreads();
    for (int off = 128; off > 0; off >>= 1) {
        if (tid < off) sh[tid] += sh[tid + off];
        __syncthreads();
    }
    float alpha_sent = sh[0];
    __syncthreads();

    float v = -INFINITY;
    if (tid < 196) {
        int m = b * 196 + tid;
        v = g_alpha_part[m] + g_alpha_part[MBIG + m] +
            g_alpha_part[2 * MBIG + m] + g_alpha_part[3 * MBIG + m];
        vals[tid] = v;
    } else if (tid == 196) {
        v = alpha_sent; vals[196] = v;
    }
    sh[tid] = v; __syncthreads();
    for (int off = 128; off > 0; off >>= 1) {
        if (tid < off) sh[tid] = fmaxf(sh[tid], sh[tid + off]);
        __syncthreads();
    }
    float mx = sh[0]; __syncthreads();

    float e = (tid < 197) ? expf(vals[tid] - mx) : 0.f;
    sh[tid] = e; __syncthreads();
    for (int off = 128; off > 0; off >>= 1) {
        if (tid < off) sh[tid] += sh[tid + off];
        __syncthreads();
    }
    float inv = 1.f / sh[0];
    if (tid < 197) {
        float w = e * inv;
        ws[tid] = w;
        out_w[b * 197 + tid] = w;
        if (tid == 196) out_beta[b] = w;
    }
    __syncthreads();

    const int h0 = tid * 4;
    const __half* hb = &g_Ah[(size_t)b * 196 * 1024 + h0];
    float4 acc = make_float4(0.f, 0.f, 0.f, 0.f);
#pragma unroll 4
    for (int p = 0; p < 196; p++) {
        uint2 u = *(const uint2*)(hb + (size_t)p * 1024);
        float2 lo = __half22float2(*(__half2*)&u.x);
        float2 hi = __half22float2(*(__half2*)&u.y);
        float wp = ws[p];
        acc.x += lo.x * wp; acc.y += lo.y * wp;
        acc.z += hi.x * wp; acc.w += hi.y * wp;
    }
    const int idx = b * 1024 + h0;
    float4 sa = *(const float4*)&g_sent_aff[idx];
    float4 ha = *(const float4*)&g_hid_aff[idx];
    float wl = ws[196];
    acc.x += sa.x * wl + ha.x; acc.y += sa.y * wl + ha.y;
    acc.z += sa.z * wl + ha.z; acc.w += sa.w * wl + ha.w;
    *(float4*)&g_ctx[idx] = acc;
}

// ------------------------------------------------------------------
extern "C" void kernel_launch(void* const* d_in, const int* in_sizes, int n_in,
                              void* d_out, int out_size)
{
    (void)in_sizes; (void)n_in; (void)out_size;
    const float* spatial   = (const float*)d_in[0];
    const float* decoder   = (const float*)d_in[1];
    const float* st        = (const float*)d_in[2];
    const float* W_sen_aff = (const float*)d_in[3];
    const float* b_sen_aff = (const float*)d_in[4];
    const float* W_sen_att = (const float*)d_in[5];
    const float* b_sen_att = (const float*)d_in[6];
    const float* W_h_aff   = (const float*)d_in[7];
    const float* b_h_aff   = (const float*)d_in[8];
    const float* W_h_att   = (const float*)d_in[9];
    const float* b_h_att   = (const float*)d_in[10];
    const float* W_v_att   = (const float*)d_in[11];
    const float* b_v_att   = (const float*)d_in[12];
    const float* W_alpha   = (const float*)d_in[13];
    // d_in[14] = b_alpha: softmax-invariant constant, dropped
    const float* W_ctx     = (const float*)d_in[15];
    const float* b_ctx     = (const float*)d_in[16];

    float* out      = (float*)d_out;
    float* out_l    = out;
    float* out_w    = out + Bz * Hz;
    float* out_beta = out + Bz * Hz + Bz * 197;

    float *sa, *ha, *st_att, *h_att, *ctx, *affp, *attp, *finp;
    cudaGetSymbolAddress((void**)&sa,     g_sent_aff);
    cudaGetSymbolAddress((void**)&ha,     g_hid_aff);
    cudaGetSymbolAddress((void**)&st_att, g_sent_att);
    cudaGetSymbolAddress((void**)&h_att,  g_hid_att);
    cudaGetSymbolAddress((void**)&ctx,    g_ctx);
    cudaGetSymbolAddress((void**)&affp,   g_aff_part);
    cudaGetSymbolAddress((void**)&attp,   g_att_part);
    cudaGetSymbolAddress((void**)&finp,   g_fin_part);

    const size_t aff_slabs = (size_t)8 * 256 * Hz;
    const size_t att_slabs = (size_t)8 * 256 * Az;
    float* affp_hid  = affp;
    float* affp_sent = affp + aff_slabs;
    float* attp_hid  = attp;
    float* attp_sent = attp + att_slabs;

    const int BIG_SMEM = NSTAGE * STG_BYTES;   // 56832
    cudaFuncSetAttribute(big_attn_mma,
                         cudaFuncAttributeMaxDynamicSharedMemorySize, BIG_SMEM);

    static cudaStream_t s2 = nullptr, s3 = nullptr;
    static cudaEvent_t ev_fork = nullptr, ev_a1 = nullptr, ev_a2 = nullptr,
                       ev_sent = nullptr;
    if (!s2) {
        cudaStreamCreateWithFlags(&s2, cudaStreamNonBlocking);
        cudaStreamCreateWithFlags(&s3, cudaStreamNonBlocking);
        cudaEventCreateWithFlags(&ev_fork, cudaEventDisableTiming);
        cudaEventCreateWithFlags(&ev_a1, cudaEventDisableTiming);
        cudaEventCreateWithFlags(&ev_a2, cudaEventDisableTiming);
        cudaEventCreateWithFlags(&ev_sent, cudaEventDisableTiming);
    }

    // ---- fork ----
    cudaEventRecord(ev_fork, 0);
    cudaStreamWaitEvent(s2, ev_fork, 0);
    cudaStreamWaitEvent(s3, ev_fork, 0);

    // s2: conversions (B, then A in two halves with events)
    convB_kernel<<<256, 256, 0, s2>>>(W_v_att);
    convA_kernel<<<12544, 256, 0, s2>>>(spatial, 0);
    cudaEventRecord(ev_a1, s2);
    convA_kernel<<<12544, 256, 0, s2>>>(spatial, HALF_ELEMS);
    cudaEventRecord(ev_a2, s2);

    // s3: sentinel chain (needed only by softmax_context)
    gemm_splitk<<<dim3(16, 4, 8), 256, 0, s3>>>(st, W_sen_aff, affp_sent, Hz);
    combine1<<<256, 256, 0, s3>>>(affp_sent, b_sen_aff, sa, Hz, 1);
    gemm_splitk<<<dim3(8, 4, 8), 256, 0, s3>>>(sa, W_sen_att, attp_sent, Az);
    combine1<<<128, 256, 0, s3>>>(attp_sent, b_sen_att, st_att, Az, 0);
    cudaEventRecord(ev_sent, s3);

    // main: hidden chain (gates the big GEMM)
    gemm_splitk<<<dim3(16, 4, 8), 256>>>(decoder, W_h_aff, affp_hid, Hz);
    combine1<<<256, 256>>>(affp_hid, b_h_aff, ha, Hz, 2);
    gemm_splitk<<<dim3(8, 4, 8), 256>>>(ha, W_h_att, attp_hid, Az);
    combine1<<<128, 256>>>(attp_hid, b_h_att, h_att, Az, 0);

    // big GEMM, split over m-halves pipelined against convA halves
    cudaStreamWaitEvent(0, ev_a1, 0);
    big_attn_mma<<<dim3(4, 196), 256, BIG_SMEM>>>(b_v_att, W_alpha, 0);
    cudaStreamWaitEvent(0, ev_a2, 0);
    big_attn_mma<<<dim3(4, 196), 256, BIG_SMEM>>>(b_v_att, W_alpha, 196 * 128);

    // softmax + context (needs sentinel chain + alpha + g_Ah)
    cudaStreamWaitEvent(0, ev_sent, 0);
    softmax_context_kernel<<<Bz, 256>>>(W_alpha, out_w, out_beta);

    // out_l = tanh(ctx @ W_ctx + b_ctx)
    gemm_splitk<<<dim3(16, 4, 8), 256>>>(ctx, W_ctx, finp, Hz);
    combine1<<<256, 256>>>(finp, b_ctx, out_l, Hz, 2);
}

// round 12
// speedup vs baseline: 1.0627x; 1.0627x over previous
#include <cuda_runtime.h>
#include <cuda_fp16.h>
#include <math.h>
#include <stdint.h>

#define Bz   256
#define Pz   196
#define Hz   1024
#define Az   512
#define MBIG (Bz * Pz)   // 50176 = 392 * 128
#define HALF_ELEMS ((size_t)MBIG * Hz / 2)

// ------------------------------------------------------------------
// device scratch (allocations forbidden)
// ------------------------------------------------------------------
__device__ float  g_sent_aff[Bz * Hz];
__device__ float  g_hid_aff [Bz * Hz];
__device__ float  g_sent_att[Bz * Az];
__device__ float  g_hid_att [Bz * Az];
__device__ float  g_alpha_part[4 * MBIG];
__device__ float  g_ctx     [Bz * Hz];
__device__ float  g_aff_part[2 * 8 * Bz * Hz];  // [hid | sent] split-K=8 slabs
__device__ float  g_att_part[2 * 8 * Bz * Az];
__device__ float  g_fin_part[8 * Bz * Hz];
__device__ __half g_Ah[(size_t)MBIG * Hz];      // spatial fp16 (103 MB)
__device__ __half g_Bh[Hz * Az];                // W_v_att fp16 [K][N]

// ------------------------------------------------------------------
__device__ __forceinline__ uint32_t smem_u32(const void* p) {
    uint32_t a;
    asm("{ .reg .u64 t; cvta.to.shared.u64 t, %1; cvt.u32.u64 %0, t; }"
        : "=r"(a) : "l"(p));
    return a;
}
__device__ __forceinline__ void cpa16(uint32_t dst, const void* src) {
    asm volatile("cp.async.cg.shared.global [%0], [%1], 16;"
                 :: "r"(dst), "l"(src) : "memory");
}
#define CP_COMMIT() asm volatile("cp.async.commit_group;" ::: "memory")
#define CP_WAIT(n)  asm volatile("cp.async.wait_group %0;" :: "n"(n) : "memory")

__device__ __forceinline__ void ldsm_x4(uint32_t* r, uint32_t addr) {
    asm volatile("ldmatrix.sync.aligned.m8n8.x4.shared.b16 {%0,%1,%2,%3}, [%4];"
                 : "=r"(r[0]), "=r"(r[1]), "=r"(r[2]), "=r"(r[3]) : "r"(addr));
}
__device__ __forceinline__ void ldsm_x4_t(uint32_t* r, uint32_t addr) {
    asm volatile("ldmatrix.sync.aligned.m8n8.x4.trans.shared.b16 {%0,%1,%2,%3}, [%4];"
                 : "=r"(r[0]), "=r"(r[1]), "=r"(r[2]), "=r"(r[3]) : "r"(addr));
}
__device__ __forceinline__ void mma16816(float* c, const uint32_t* a, const uint32_t* b) {
    asm volatile(
        "mma.sync.aligned.m16n8k16.row.col.f32.f16.f16.f32 "
        "{%0,%1,%2,%3}, {%4,%5,%6,%7}, {%8,%9}, {%0,%1,%2,%3};"
        : "+f"(c[0]), "+f"(c[1]), "+f"(c[2]), "+f"(c[3])
        : "r"(a[0]), "r"(a[1]), "r"(a[2]), "r"(a[3]), "r"(b[0]), "r"(b[1]));
}
__device__ __forceinline__ uint32_t tanh_f16x2(uint32_t x) {
    uint32_t y;
    asm("tanh.approx.f16x2 %0, %1;" : "=r"(y) : "r"(x));
    return y;
}

// ------------------------------------------------------------------
// fp32 -> fp16 conversions (streaming, full MLP); offset for split launch
// ------------------------------------------------------------------
__global__ void convA_kernel(const float* __restrict__ Sp, size_t off) {
    size_t base = off + ((size_t)blockIdx.x * 256 + threadIdx.x) * 8;
    float4 x0 = *(const float4*)&Sp[base];
    float4 x1 = *(const float4*)&Sp[base + 4];
    __half2 h[4];
    h[0] = __floats2half2_rn(x0.x, x0.y);
    h[1] = __floats2half2_rn(x0.z, x0.w);
    h[2] = __floats2half2_rn(x1.x, x1.y);
    h[3] = __floats2half2_rn(x1.z, x1.w);
    *(uint4*)&g_Ah[base] = *(uint4*)h;
}
__global__ void convB_kernel(const float* __restrict__ Wv) {
    size_t base = ((size_t)blockIdx.x * 256 + threadIdx.x) * 8;
    float4 x0 = *(const float4*)&Wv[base];
    float4 x1 = *(const float4*)&Wv[base + 4];
    __half2 h[4];
    h[0] = __floats2half2_rn(x0.x, x0.y);
    h[1] = __floats2half2_rn(x0.z, x0.w);
    h[2] = __floats2half2_rn(x1.x, x1.y);
    h[3] = __floats2half2_rn(x1.z, x1.w);
    *(uint4*)&g_Bh[base] = *(uint4*)h;
}

// ------------------------------------------------------------------
// big fused attention GEMM on HMMA, BM=128 BN=128 BK=32
// 3-stage cp.async ring. grid (4 chunks, m-tiles), m_base for split launch.
// ------------------------------------------------------------------
#define AS_STRIDE 80
#define BS_STRIDE 272
#define AS_BYTES  10240
#define BS_BYTES  8704
#define STG_BYTES (AS_BYTES + BS_BYTES)
#define NSTAGE    3

__global__ void __launch_bounds__(256, 2)
big_attn_mma(const float* __restrict__ bv,   // (512)
             const float* __restrict__ Wa,   // (512)
             int m_base)
{
    extern __shared__ char dyn[];
    __shared__ float red[128 * 4];

    const int tid  = threadIdx.x;
    const int wid  = tid >> 5;
    const int lane = tid & 31;
    const int wm   = wid & 1;
    const int wn   = wid >> 1;
    const int m0   = m_base + blockIdx.y * 128;
    const int n0g  = blockIdx.x * 128;

    const uint32_t dyn_s = smem_u32(dyn);

    float acc[4][4][4] = {};

    auto prefetch = [&](int kc, int s) {
        const uint32_t as = dyn_s + s * STG_BYTES;
        const uint32_t bs = as + AS_BYTES;
        const int k0 = kc * 32;
#pragma unroll
        for (int g = 0; g < 2; g++) {
            int idx = g * 256 + tid;
            int row = idx >> 2, c = idx & 3;
            cpa16(as + row * AS_STRIDE + c * 16,
                  &g_Ah[(size_t)(m0 + row) * 1024 + k0 + c * 8]);
        }
#pragma unroll
        for (int g = 0; g < 2; g++) {
            int idx = g * 256 + tid;
            int row = idx >> 4, c = idx & 15;
            cpa16(bs + row * BS_STRIDE + c * 16,
                  &g_Bh[(size_t)(k0 + row) * 512 + n0g + c * 8]);
        }
        CP_COMMIT();
    };

    prefetch(0, 0);
    prefetch(1, 1);

    int stage = 0;
    for (int kc = 0; kc < 32; kc++) {
        if (kc < 31) { CP_WAIT(1); } else { CP_WAIT(0); }
        __syncthreads();

        if (kc < 30) {
            int ps = stage + 2; if (ps >= NSTAGE) ps -= NSTAGE;
            prefetch(kc + 2, ps);
        }

        const uint32_t as = dyn_s + stage * STG_BYTES;
        const uint32_t bs = as + AS_BYTES;

#pragma unroll
        for (int k16 = 0; k16 < 2; k16++) {
            uint32_t a_frag[4][4];
            uint32_t b_frag[4][2];
#pragma unroll
            for (int mt = 0; mt < 4; mt++) {
                int row = wm * 64 + mt * 16 + (lane & 15);
                int col = k16 * 16 + ((lane >> 4) << 3);
                ldsm_x4(a_frag[mt], as + row * AS_STRIDE + col * 2);
            }
#pragma unroll
            for (int p = 0; p < 2; p++) {
                int krow = k16 * 16 + ((lane >> 3) & 1) * 8 + (lane & 7);
                int col  = wn * 32 + p * 16 + ((lane >> 4) << 3);
                uint32_t r[4];
                ldsm_x4_t(r, bs + krow * BS_STRIDE + col * 2);
                b_frag[2 * p][0] = r[0]; b_frag[2 * p][1] = r[1];
                b_frag[2 * p + 1][0] = r[2]; b_frag[2 * p + 1][1] = r[3];
            }
#pragma unroll
            for (int mt = 0; mt < 4; mt++)
#pragma unroll
                for (int nt = 0; nt < 4; nt++)
                    mma16816(acc[mt][nt], a_frag[mt], b_frag[nt]);
        }
        stage++; if (stage >= NSTAGE) stage = 0;
    }
    __syncthreads();

    // ---- epilogue: alpha_part[m] = sum_n tanh(D + bv + hid_att) * Wa ----
    // (MUFU tanh.f16x2: hidden under other CTAs' tensor mainloops; the FMA
    //  rational-tanh variant measured +15us — do not reintroduce.)
    const int lane4 = lane & 3, laned4 = lane >> 2;
    float bvv[8], waa[8];
#pragma unroll
    for (int nt = 0; nt < 4; nt++) {
        int ng = n0g + wn * 32 + nt * 8 + lane4 * 2;
        bvv[2 * nt] = bv[ng];     bvv[2 * nt + 1] = bv[ng + 1];
        waa[2 * nt] = Wa[ng];     waa[2 * nt + 1] = Wa[ng + 1];
    }
#pragma unroll
    for (int mt = 0; mt < 4; mt++) {
        float srow[2] = {0.f, 0.f};
#pragma unroll
        for (int h = 0; h < 2; h++) {
            int rloc = wm * 64 + mt * 16 + laned4 + h * 8;
            int bb = (m0 + rloc) / Pz;
            const float* ha = &g_hid_att[(size_t)bb * Az + n0g];
#pragma unroll
            for (int nt = 0; nt < 4; nt++) {
                int cl = wn * 32 + nt * 8 + lane4 * 2;
                float z0 = acc[mt][nt][2 * h]     + bvv[2 * nt]     + ha[cl];
                float z1 = acc[mt][nt][2 * h + 1] + bvv[2 * nt + 1] + ha[cl + 1];
                __half2 zh = __floats2half2_rn(z0, z1);
                uint32_t th = tanh_f16x2(*(uint32_t*)&zh);
                float2 tf = __half22float2(*(__half2*)&th);
                srow[h] += tf.x * waa[2 * nt] + tf.y * waa[2 * nt + 1];
            }
        }
#pragma unroll
        for (int h = 0; h < 2; h++) {
            float s = srow[h];
            s += __shfl_xor_sync(0xffffffffu, s, 1);
            s += __shfl_xor_sync(0xffffffffu, s, 2);
            if (lane4 == 0) {
                int rloc = wm * 64 + mt * 16 + laned4 + h * 8;
                red[rloc * 4 + wn] = s;
            }
        }
    }
    __syncthreads();
    if (tid < 128) {
        float s = red[tid * 4] + red[tid * 4 + 1] + red[tid * 4 + 2] + red[tid * 4 + 3];
        g_alpha_part[(size_t)blockIdx.x * MBIG + m0 + tid] = s;
    }
}

// ------------------------------------------------------------------
// split-K=8 fp32 GEMM, single job per launch (z = 8 K-splits).
// Register double-buffer: LDG for iter i+1 issued BEFORE compute of
// iter i, hiding the ~600cyc DRAM/L2 latency under the FMA block.
// ------------------------------------------------------------------
__global__ void gemm_splitk(const float* __restrict__ A,
                            const float* __restrict__ W,
                            float* __restrict__ part, int N)
{
    __shared__ __align__(16) float As[16][68];
    __shared__ __align__(16) float Bs[16][68];
    const int ks = blockIdx.z;
    const int tid = threadIdx.x;
    const int tx = tid & 15, ty = tid >> 4;
    const int m0 = blockIdx.y * 64, n0 = blockIdx.x * 64;
    const int kbase = ks * 128;

    const int arow = tid >> 2, acg = (tid & 3) * 4;
    const int brow = tid >> 4, bcol = (tid & 15) * 4;

    float acc[4][4] = {};

    // prologue load (iteration 0)
    float4 av = *(const float4*)&A[(size_t)(m0 + arow) * 1024 + kbase + acg];
    float4 bw = *(const float4*)&W[(size_t)(kbase + brow) * N + n0 + bcol];

    for (int it = 0; it < 8; it++) {
        // publish current tile
        As[acg + 0][arow] = av.x; As[acg + 1][arow] = av.y;
        As[acg + 2][arow] = av.z; As[acg + 3][arow] = av.w;
        *(float4*)&Bs[brow][bcol] = bw;
        __syncthreads();

        // issue next iteration's LDGs (latency overlapped with compute)
        if (it < 7) {
            int k0 = kbase + (it + 1) * 16;
            av = *(const float4*)&A[(size_t)(m0 + arow) * 1024 + k0 + acg];
            bw = *(const float4*)&W[(size_t)(k0 + brow) * N + n0 + bcol];
        }

#pragma unroll
        for (int k = 0; k < 16; k++) {
            float4 a4 = *(const float4*)&As[k][ty * 4];
            float4 b4 = *(const float4*)&Bs[k][tx * 4];
            float a[4] = {a4.x, a4.y, a4.z, a4.w};
            float b[4] = {b4.x, b4.y, b4.z, b4.w};
#pragma unroll
            for (int i = 0; i < 4; i++)
#pragma unroll
                for (int j = 0; j < 4; j++) acc[i][j] += a[i] * b[j];
        }
        __syncthreads();
    }

    float* out = part + (size_t)ks * 256 * N;
#pragma unroll
    for (int i = 0; i < 4; i++) {
        int m = m0 + ty * 4 + i;
#pragma unroll
        for (int j = 0; j < 4; j++)
            out[(size_t)m * N + n0 + tx * 4 + j] = acc[i][j];
    }
}

// combine 8 split-K partials + bias + activation (0=none,1=relu,2=tanh)
__global__ void combine1(const float* __restrict__ part,
                         const float* __restrict__ bias,
                         float* __restrict__ o, int N, int act)
{
    const size_t e = ((size_t)blockIdx.x * 256 + threadIdx.x) * 4;
    const size_t slab = (size_t)256 * N;
    float4 s = *(const float4*)(part + e);
#pragma unroll
    for (int t = 1; t < 8; t++) {
        float4 q = *(const float4*)(part + t * slab + e);
        s.x += q.x; s.y += q.y; s.z += q.z; s.w += q.w;
    }
    const int n = (int)(e & (size_t)(N - 1));
    float4 bvec = *(const float4*)&bias[n];
    s.x += bvec.x; s.y += bvec.y; s.z += bvec.z; s.w += bvec.w;
    if (act == 1) {
        s.x = fmaxf(s.x, 0.f); s.y = fmaxf(s.y, 0.f);
        s.z = fmaxf(s.z, 0.f); s.w = fmaxf(s.w, 0.f);
    } else if (act == 2) {
        s.x = tanhf(s.x); s.y = tanhf(s.y); s.z = tanhf(s.z); s.w = tanhf(s.w);
    }
    *(float4*)(o + e) = s;
}

// ------------------------------------------------------------------
// merged softmax (197 logits incl. sentinel) + context per batch
// context reads fp16 g_Ah (half the traffic of fp32 spatial)
// ------------------------------------------------------------------
__global__ void softmax_context_kernel(const float* __restrict__ Wa,
                                       float* __restrict__ out_w,
                                       float* __restrict__ out_beta)
{
    const int b = blockIdx.x;
    const int tid = threadIdx.x;
    __shared__ float sh[256];
    __shared__ float vals[197];
    __shared__ float ws[197];

    float s = 0.f;
    for (int a = tid; a < 512; a += 256)
        s += tanhf(g_sent_att[b * 512 + a] + g_hid_att[b * 512 + a]) * Wa[a];
    sh[tid] = s; __syncthreads();
    for (int off = 128; off > 0; off >>= 1) {
        if (tid < off) sh[tid] += sh[tid + off];
        __syncthreads();
    }
    float alpha_sent = sh[0];
    __syncthreads();

    float v = -INFINITY;
    if (tid < 196) {
        int m = b * 196 + tid;
        v = g_alpha_part[m] + g_alpha_part[MBIG + m] +
            g_alpha_part[2 * MBIG + m] + g_alpha_part[3 * MBIG + m];
        vals[tid] = v;
    } else if (tid == 196) {
        v = alpha_sent; vals[196] = v;
    }
    sh[tid] = v; __syncthreads();
    for (int off = 128; off > 0; off >>= 1) {
        if (tid < off) sh[tid] = fmaxf(sh[tid], sh[tid + off]);
        __syncthreads();
    }
    float mx = sh[0]; __syncthreads();

    float e = (tid < 197) ? expf(vals[tid] - mx) : 0.f;
    sh[tid] = e; __syncthreads();
    for (int off = 128; off > 0; off >>= 1) {
        if (tid < off) sh[tid] += sh[tid + off];
        __syncthreads();
    }
    float inv = 1.f / sh[0];
    if (tid < 197) {
        float w = e * inv;
        ws[tid] = w;
        out_w[b * 197 + tid] = w;
        if (tid == 196) out_beta[b] = w;
    }
    __syncthreads();

    const int h0 = tid * 4;
    const __half* hb = &g_Ah[(size_t)b * 196 * 1024 + h0];
    float4 acc = make_float4(0.f, 0.f, 0.f, 0.f);
#pragma unroll 4
    for (int p = 0; p < 196; p++) {
        uint2 u = *(const uint2*)(hb + (size_t)p * 1024);
        float2 lo = __half22float2(*(__half2*)&u.x);
        float2 hi = __half22float2(*(__half2*)&u.y);
        float wp = ws[p];
        acc.x += lo.x * wp; acc.y += lo.y * wp;
        acc.z += hi.x * wp; acc.w += hi.y * wp;
    }
    const int idx = b * 1024 + h0;
    float4 sa = *(const float4*)&g_sent_aff[idx];
    float4 ha = *(const float4*)&g_hid_aff[idx];
    float wl = ws[196];
    acc.x += sa.x * wl + ha.x; acc.y += sa.y * wl + ha.y;
    acc.z += sa.z * wl + ha.z; acc.w += sa.w * wl + ha.w;
    *(float4*)&g_ctx[idx] = acc;
}

// ------------------------------------------------------------------
extern "C" void kernel_launch(void* const* d_in, const int* in_sizes, int n_in,
                              void* d_out, int out_size)
{
    (void)in_sizes; (void)n_in; (void)out_size;
    const float* spatial   = (const float*)d_in[0];
    const float* decoder   = (const float*)d_in[1];
    const float* st        = (const float*)d_in[2];
    const float* W_sen_aff = (const float*)d_in[3];
    const float* b_sen_aff = (const float*)d_in[4];
    const float* W_sen_att = (const float*)d_in[5];
    const float* b_sen_att = (const float*)d_in[6];
    const float* W_h_aff   = (const float*)d_in[7];
    const float* b_h_aff   = (const float*)d_in[8];
    const float* W_h_att   = (const float*)d_in[9];
    const float* b_h_att   = (const float*)d_in[10];
    const float* W_v_att   = (const float*)d_in[11];
    const float* b_v_att   = (const float*)d_in[12];
    const float* W_alpha   = (const float*)d_in[13];
    // d_in[14] = b_alpha: softmax-invariant constant, dropped
    const float* W_ctx     = (const float*)d_in[15];
    const float* b_ctx     = (const float*)d_in[16];

    float* out      = (float*)d_out;
    float* out_l    = out;
    float* out_w    = out + Bz * Hz;
    float* out_beta = out + Bz * Hz + Bz * 197;

    float *sa, *ha, *st_att, *h_att, *ctx, *affp, *attp, *finp;
    cudaGetSymbolAddress((void**)&sa,     g_sent_aff);
    cudaGetSymbolAddress((void**)&ha,     g_hid_aff);
    cudaGetSymbolAddress((void**)&st_att, g_sent_att);
    cudaGetSymbolAddress((void**)&h_att,  g_hid_att);
    cudaGetSymbolAddress((void**)&ctx,    g_ctx);
    cudaGetSymbolAddress((void**)&affp,   g_aff_part);
    cudaGetSymbolAddress((void**)&attp,   g_att_part);
    cudaGetSymbolAddress((void**)&finp,   g_fin_part);

    const size_t aff_slabs = (size_t)8 * 256 * Hz;
    const size_t att_slabs = (size_t)8 * 256 * Az;
    float* affp_hid  = affp;
    float* affp_sent = affp + aff_slabs;
    float* attp_hid  = attp;
    float* attp_sent = attp + att_slabs;

    const int BIG_SMEM = NSTAGE * STG_BYTES;   // 56832
    cudaFuncSetAttribute(big_attn_mma,
                         cudaFuncAttributeMaxDynamicSharedMemorySize, BIG_SMEM);

    static cudaStream_t s2 = nullptr, s3 = nullptr;
    static cudaEvent_t ev_fork = nullptr, ev_a1 = nullptr, ev_a2 = nullptr,
                       ev_sent = nullptr;
    if (!s2) {
        cudaStreamCreateWithFlags(&s2, cudaStreamNonBlocking);
        cudaStreamCreateWithFlags(&s3, cudaStreamNonBlocking);
        cudaEventCreateWithFlags(&ev_fork, cudaEventDisableTiming);
        cudaEventCreateWithFlags(&ev_a1, cudaEventDisableTiming);
        cudaEventCreateWithFlags(&ev_a2, cudaEventDisableTiming);
        cudaEventCreateWithFlags(&ev_sent, cudaEventDisableTiming);
    }

    // ---- fork ----
    cudaEventRecord(ev_fork, 0);
    cudaStreamWaitEvent(s2, ev_fork, 0);
    cudaStreamWaitEvent(s3, ev_fork, 0);

    // s2: conversions (B, then A in two halves with events)
    convB_kernel<<<256, 256, 0, s2>>>(W_v_att);
    convA_kernel<<<12544, 256, 0, s2>>>(spatial, 0);
    cudaEventRecord(ev_a1, s2);
    convA_kernel<<<12544, 256, 0, s2>>>(spatial, HALF_ELEMS);
    cudaEventRecord(ev_a2, s2);

    // s3: sentinel chain (needed only by softmax_context)
    gemm_splitk<<<dim3(16, 4, 8), 256, 0, s3>>>(st, W_sen_aff, affp_sent, Hz);
    combine1<<<256, 256, 0, s3>>>(affp_sent, b_sen_aff, sa, Hz, 1);
    gemm_splitk<<<dim3(8, 4, 8), 256, 0, s3>>>(sa, W_sen_att, attp_sent, Az);
    combine1<<<128, 256, 0, s3>>>(attp_sent, b_sen_att, st_att, Az, 0);
    cudaEventRecord(ev_sent, s3);

    // main: hidden chain (gates the big GEMM)
    gemm_splitk<<<dim3(16, 4, 8), 256>>>(decoder, W_h_aff, affp_hid, Hz);
    combine1<<<256, 256>>>(affp_hid, b_h_aff, ha, Hz, 2);
    gemm_splitk<<<dim3(8, 4, 8), 256>>>(ha, W_h_att, attp_hid, Az);
    combine1<<<128, 256>>>(attp_hid, b_h_att, h_att, Az, 0);

    // big GEMM, split over m-halves pipelined against convA halves
    cudaStreamWaitEvent(0, ev_a1, 0);
    big_attn_mma<<<dim3(4, 196), 256, BIG_SMEM>>>(b_v_att, W_alpha, 0);
    cudaStreamWaitEvent(0, ev_a2, 0);
    big_attn_mma<<<dim3(4, 196), 256, BIG_SMEM>>>(b_v_att, W_alpha, 196 * 128);

    // softmax + context (needs sentinel chain + alpha + g_Ah)
    cudaStreamWaitEvent(0, ev_sent, 0);
    softmax_context_kernel<<<Bz, 256>>>(W_alpha, out_w, out_beta);

    // out_l = tanh(ctx @ W_ctx + b_ctx)
    gemm_splitk<<<dim3(16, 4, 8), 256>>>(ctx, W_ctx, finp, Hz);
    combine1<<<256, 256>>>(finp, b_ctx, out_l, Hz, 2);
}

// round 13
// speedup vs baseline: 1.0903x; 1.0259x over previous
#include <cuda_runtime.h>
#include <cuda_fp16.h>
#include <math.h>
#include <stdint.h>

#define Bz   256
#define Pz   196
#define Hz   1024
#define Az   512
#define MBIG (Bz * Pz)   // 50176 = 392 * 128

// ------------------------------------------------------------------
// device scratch (allocations forbidden)
// ------------------------------------------------------------------
__device__ float  g_sent_aff[Bz * Hz];
__device__ float  g_hid_aff [Bz * Hz];
__device__ float  g_sent_att[Bz * Az];
__device__ float  g_hid_att [Bz * Az];
__device__ float  g_alpha_part[4 * MBIG];
__device__ float  g_ctx     [Bz * Hz];
__device__ float  g_aff_part[2 * 8 * Bz * Hz];  // [hid | sent] split-K=8 slabs
__device__ float  g_att_part[2 * 8 * Bz * Az];
__device__ float  g_fin_part[8 * Bz * Hz];
__device__ __half g_Ah[(size_t)MBIG * Hz];      // spatial fp16 (103 MB)
__device__ __half g_Bh[Hz * Az];                // W_v_att fp16 [K][N]

// ------------------------------------------------------------------
__device__ __forceinline__ uint32_t smem_u32(const void* p) {
    uint32_t a;
    asm("{ .reg .u64 t; cvta.to.shared.u64 t, %1; cvt.u32.u64 %0, t; }"
        : "=r"(a) : "l"(p));
    return a;
}
__device__ __forceinline__ void cpa16(uint32_t dst, const void* src) {
    asm volatile("cp.async.cg.shared.global [%0], [%1], 16;"
                 :: "r"(dst), "l"(src) : "memory");
}
#define CP_COMMIT() asm volatile("cp.async.commit_group;" ::: "memory")
#define CP_WAIT(n)  asm volatile("cp.async.wait_group %0;" :: "n"(n) : "memory")

__device__ __forceinline__ void ldsm_x4(uint32_t* r, uint32_t addr) {
    asm volatile("ldmatrix.sync.aligned.m8n8.x4.shared.b16 {%0,%1,%2,%3}, [%4];"
                 : "=r"(r[0]), "=r"(r[1]), "=r"(r[2]), "=r"(r[3]) : "r"(addr));
}
__device__ __forceinline__ void ldsm_x4_t(uint32_t* r, uint32_t addr) {
    asm volatile("ldmatrix.sync.aligned.m8n8.x4.trans.shared.b16 {%0,%1,%2,%3}, [%4];"
                 : "=r"(r[0]), "=r"(r[1]), "=r"(r[2]), "=r"(r[3]) : "r"(addr));
}
__device__ __forceinline__ void mma16816(float* c, const uint32_t* a, const uint32_t* b) {
    asm volatile(
        "mma.sync.aligned.m16n8k16.row.col.f32.f16.f16.f32 "
        "{%0,%1,%2,%3}, {%4,%5,%6,%7}, {%8,%9}, {%0,%1,%2,%3};"
        : "+f"(c[0]), "+f"(c[1]), "+f"(c[2]), "+f"(c[3])
        : "r"(a[0]), "r"(a[1]), "r"(a[2]), "r"(a[3]), "r"(b[0]), "r"(b[1]));
}
__device__ __forceinline__ uint32_t tanh_f16x2(uint32_t x) {
    uint32_t y;
    asm("tanh.approx.f16x2 %0, %1;" : "=r"(y) : "r"(x));
    return y;
}

// ------------------------------------------------------------------
// fp32 -> fp16 conversions (streaming, full MLP)
// ------------------------------------------------------------------
__global__ void convA_kernel(const float* __restrict__ Sp) {
    size_t base = ((size_t)blockIdx.x * 256 + threadIdx.x) * 8;
    float4 x0 = *(const float4*)&Sp[base];
    float4 x1 = *(const float4*)&Sp[base + 4];
    __half2 h[4];
    h[0] = __floats2half2_rn(x0.x, x0.y);
    h[1] = __floats2half2_rn(x0.z, x0.w);
    h[2] = __floats2half2_rn(x1.x, x1.y);
    h[3] = __floats2half2_rn(x1.z, x1.w);
    *(uint4*)&g_Ah[base] = *(uint4*)h;
}
__global__ void convB_kernel(const float* __restrict__ Wv) {
    size_t base = ((size_t)blockIdx.x * 256 + threadIdx.x) * 8;
    float4 x0 = *(const float4*)&Wv[base];
    float4 x1 = *(const float4*)&Wv[base + 4];
    __half2 h[4];
    h[0] = __floats2half2_rn(x0.x, x0.y);
    h[1] = __floats2half2_rn(x0.z, x0.w);
    h[2] = __floats2half2_rn(x1.x, x1.y);
    h[3] = __floats2half2_rn(x1.z, x1.w);
    *(uint4*)&g_Bh[base] = *(uint4*)h;
}

// ------------------------------------------------------------------
// big fused attention GEMM on HMMA, BM=128 BN=128 BK=32
// 3-stage cp.async ring. SINGLE launch, grid (4 chunks, 392 m-tiles):
// one ramp/drain instead of two (m-half split measured as wave-drain waste).
// ------------------------------------------------------------------
#define AS_STRIDE 80
#define BS_STRIDE 272
#define AS_BYTES  10240
#define BS_BYTES  8704
#define STG_BYTES (AS_BYTES + BS_BYTES)
#define NSTAGE    3

__global__ void __launch_bounds__(256, 2)
big_attn_mma(const float* __restrict__ bv,   // (512)
             const float* __restrict__ Wa)   // (512)
{
    extern __shared__ char dyn[];
    __shared__ float red[128 * 4];

    const int tid  = threadIdx.x;
    const int wid  = tid >> 5;
    const int lane = tid & 31;
    const int wm   = wid & 1;
    const int wn   = wid >> 1;
    const int m0   = blockIdx.y * 128;
    const int n0g  = blockIdx.x * 128;

    const uint32_t dyn_s = smem_u32(dyn);

    float acc[4][4][4] = {};

    auto prefetch = [&](int kc, int s) {
        const uint32_t as = dyn_s + s * STG_BYTES;
        const uint32_t bs = as + AS_BYTES;
        const int k0 = kc * 32;
#pragma unroll
        for (int g = 0; g < 2; g++) {
            int idx = g * 256 + tid;
            int row = idx >> 2, c = idx & 3;
            cpa16(as + row * AS_STRIDE + c * 16,
                  &g_Ah[(size_t)(m0 + row) * 1024 + k0 + c * 8]);
        }
#pragma unroll
        for (int g = 0; g < 2; g++) {
            int idx = g * 256 + tid;
            int row = idx >> 4, c = idx & 15;
            cpa16(bs + row * BS_STRIDE + c * 16,
                  &g_Bh[(size_t)(k0 + row) * 512 + n0g + c * 8]);
        }
        CP_COMMIT();
    };

    prefetch(0, 0);
    prefetch(1, 1);

    int stage = 0;
    for (int kc = 0; kc < 32; kc++) {
        if (kc < 31) { CP_WAIT(1); } else { CP_WAIT(0); }
        __syncthreads();

        if (kc < 30) {
            int ps = stage + 2; if (ps >= NSTAGE) ps -= NSTAGE;
            prefetch(kc + 2, ps);
        }

        const uint32_t as = dyn_s + stage * STG_BYTES;
        const uint32_t bs = as + AS_BYTES;

#pragma unroll
        for (int k16 = 0; k16 < 2; k16++) {
            uint32_t a_frag[4][4];
            uint32_t b_frag[4][2];
#pragma unroll
            for (int mt = 0; mt < 4; mt++) {
                int row = wm * 64 + mt * 16 + (lane & 15);
                int col = k16 * 16 + ((lane >> 4) << 3);
                ldsm_x4(a_frag[mt], as + row * AS_STRIDE + col * 2);
            }
#pragma unroll
            for (int p = 0; p < 2; p++) {
                int krow = k16 * 16 + ((lane >> 3) & 1) * 8 + (lane & 7);
                int col  = wn * 32 + p * 16 + ((lane >> 4) << 3);
                uint32_t r[4];
                ldsm_x4_t(r, bs + krow * BS_STRIDE + col * 2);
                b_frag[2 * p][0] = r[0]; b_frag[2 * p][1] = r[1];
                b_frag[2 * p + 1][0] = r[2]; b_frag[2 * p + 1][1] = r[3];
            }
#pragma unroll
            for (int mt = 0; mt < 4; mt++)
#pragma unroll
                for (int nt = 0; nt < 4; nt++)
                    mma16816(acc[mt][nt], a_frag[mt], b_frag[nt]);
        }
        stage++; if (stage >= NSTAGE) stage = 0;
    }
    __syncthreads();

    // ---- epilogue: alpha_part[m] = sum_n tanh(D + bv + hid_att) * Wa ----
    // (MUFU tanh.f16x2 is hidden under other CTAs' mainloops; FMA rational
    //  tanh measured +15us — keep MUFU.)
    const int lane4 = lane & 3, laned4 = lane >> 2;
    float bvv[8], waa[8];
#pragma unroll
    for (int nt = 0; nt < 4; nt++) {
        int ng = n0g + wn * 32 + nt * 8 + lane4 * 2;
        bvv[2 * nt] = bv[ng];     bvv[2 * nt + 1] = bv[ng + 1];
        waa[2 * nt] = Wa[ng];     waa[2 * nt + 1] = Wa[ng + 1];
    }
#pragma unroll
    for (int mt = 0; mt < 4; mt++) {
        float srow[2] = {0.f, 0.f};
#pragma unroll
        for (int h = 0; h < 2; h++) {
            int rloc = wm * 64 + mt * 16 + laned4 + h * 8;
            int bb = (m0 + rloc) / Pz;
            const float* ha = &g_hid_att[(size_t)bb * Az + n0g];
#pragma unroll
            for (int nt = 0; nt < 4; nt++) {
                int cl = wn * 32 + nt * 8 + lane4 * 2;
                float z0 = acc[mt][nt][2 * h]     + bvv[2 * nt]     + ha[cl];
                float z1 = acc[mt][nt][2 * h + 1] + bvv[2 * nt + 1] + ha[cl + 1];
                __half2 zh = __floats2half2_rn(z0, z1);
                uint32_t th = tanh_f16x2(*(uint32_t*)&zh);
                float2 tf = __half22float2(*(__half2*)&th);
                srow[h] += tf.x * waa[2 * nt] + tf.y * waa[2 * nt + 1];
            }
        }
#pragma unroll
        for (int h = 0; h < 2; h++) {
            float s = srow[h];
            s += __shfl_xor_sync(0xffffffffu, s, 1);
            s += __shfl_xor_sync(0xffffffffu, s, 2);
            if (lane4 == 0) {
                int rloc = wm * 64 + mt * 16 + laned4 + h * 8;
                red[rloc * 4 + wn] = s;
            }
        }
    }
    __syncthreads();
    if (tid < 128) {
        float s = red[tid * 4] + red[tid * 4 + 1] + red[tid * 4 + 2] + red[tid * 4 + 3];
        g_alpha_part[(size_t)blockIdx.x * MBIG + m0 + tid] = s;
    }
}

// ------------------------------------------------------------------
// split-K=8 fp32 GEMM, single job per launch (z = 8 K-splits).
// Register double-buffered loads (measured ~1us better; LDS/issue-bound).
// ------------------------------------------------------------------
__global__ void gemm_splitk(const float* __restrict__ A,
                            const float* __restrict__ W,
                            float* __restrict__ part, int N)
{
    __shared__ __align__(16) float As[16][68];
    __shared__ __align__(16) float Bs[16][68];
    const int ks = blockIdx.z;
    const int tid = threadIdx.x;
    const int tx = tid & 15, ty = tid >> 4;
    const int m0 = blockIdx.y * 64, n0 = blockIdx.x * 64;
    const int kbase = ks * 128;

    const int arow = tid >> 2, acg = (tid & 3) * 4;
    const int brow = tid >> 4, bcol = (tid & 15) * 4;

    float acc[4][4] = {};

    float4 av = *(const float4*)&A[(size_t)(m0 + arow) * 1024 + kbase + acg];
    float4 bw = *(const float4*)&W[(size_t)(kbase + brow) * N + n0 + bcol];

    for (int it = 0; it < 8; it++) {
        As[acg + 0][arow] = av.x; As[acg + 1][arow] = av.y;
        As[acg + 2][arow] = av.z; As[acg + 3][arow] = av.w;
        *(float4*)&Bs[brow][bcol] = bw;
        __syncthreads();

        if (it < 7) {
            int k0 = kbase + (it + 1) * 16;
            av = *(const float4*)&A[(size_t)(m0 + arow) * 1024 + k0 + acg];
            bw = *(const float4*)&W[(size_t)(k0 + brow) * N + n0 + bcol];
        }

#pragma unroll
        for (int k = 0; k < 16; k++) {
            float4 a4 = *(const float4*)&As[k][ty * 4];
            float4 b4 = *(const float4*)&Bs[k][tx * 4];
            float a[4] = {a4.x, a4.y, a4.z, a4.w};
            float b[4] = {b4.x, b4.y, b4.z, b4.w};
#pragma unroll
            for (int i = 0; i < 4; i++)
#pragma unroll
                for (int j = 0; j < 4; j++) acc[i][j] += a[i] * b[j];
        }
        __syncthreads();
    }

    float* out = part + (size_t)ks * 256 * N;
#pragma unroll
    for (int i = 0; i < 4; i++) {
        int m = m0 + ty * 4 + i;
#pragma unroll
        for (int j = 0; j < 4; j++)
            out[(size_t)m * N + n0 + tx * 4 + j] = acc[i][j];
    }
}

// combine 8 split-K partials + bias + activation (0=none,1=relu,2=tanh)
__global__ void combine1(const float* __restrict__ part,
                         const float* __restrict__ bias,
                         float* __restrict__ o, int N, int act)
{
    const size_t e = ((size_t)blockIdx.x * 256 + threadIdx.x) * 4;
    const size_t slab = (size_t)256 * N;
    float4 s = *(const float4*)(part + e);
#pragma unroll
    for (int t = 1; t < 8; t++) {
        float4 q = *(const float4*)(part + t * slab + e);
        s.x += q.x; s.y += q.y; s.z += q.z; s.w += q.w;
    }
    const int n = (int)(e & (size_t)(N - 1));
    float4 bvec = *(const float4*)&bias[n];
    s.x += bvec.x; s.y += bvec.y; s.z += bvec.z; s.w += bvec.w;
    if (act == 1) {
        s.x = fmaxf(s.x, 0.f); s.y = fmaxf(s.y, 0.f);
        s.z = fmaxf(s.z, 0.f); s.w = fmaxf(s.w, 0.f);
    } else if (act == 2) {
        s.x = tanhf(s.x); s.y = tanhf(s.y); s.z = tanhf(s.z); s.w = tanhf(s.w);
    }
    *(float4*)(o + e) = s;
}

// ------------------------------------------------------------------
// merged softmax (197 logits incl. sentinel) + context per batch
// ------------------------------------------------------------------
__global__ void softmax_context_kernel(const float* __restrict__ Wa,
                                       float* __restrict__ out_w,
                                       float* __restrict__ out_beta)
{
    const int b = blockIdx.x;
    const int tid = threadIdx.x;
    __shared__ float sh[256];
    __shared__ float vals[197];
    __shared__ float ws[197];

    float s = 0.f;
    for (int a = tid; a < 512; a += 256)
        s += tanhf(g_sent_att[b * 512 + a] + g_hid_att[b * 512 + a]) * Wa[a];
    sh[tid] = s; __syncthreads();
    for (int off = 128; off > 0; off >>= 1) {
        if (tid < off) sh[tid] += sh[tid + off];
        __syncthreads();
    }
    float alpha_sent = sh[0];
    __syncthreads();

    float v = -INFINITY;
    if (tid < 196) {
        int m = b * 196 + tid;
        v = g_alpha_part[m] + g_alpha_part[MBIG + m] +
            g_alpha_part[2 * MBIG + m] + g_alpha_part[3 * MBIG + m];
        vals[tid] = v;
    } else if (tid == 196) {
        v = alpha_sent; vals[196] = v;
    }
    sh[tid] = v; __syncthreads();
    for (int off = 128; off > 0; off >>= 1) {
        if (tid < off) sh[tid] = fmaxf(sh[tid], sh[tid + off]);
        __syncthreads();
    }
    float mx = sh[0]; __syncthreads();

    float e = (tid < 197) ? expf(vals[tid] - mx) : 0.f;
    sh[tid] = e; __syncthreads();
    for (int off = 128; off > 0; off >>= 1) {
        if (tid < off) sh[tid] += sh[tid + off];
        __syncthreads();
    }
    float inv = 1.f / sh[0];
    if (tid < 197) {
        float w = e * inv;
        ws[tid] = w;
        out_w[b * 197 + tid] = w;
        if (tid == 196) out_beta[b] = w;
    }
    __syncthreads();

    const int h0 = tid * 4;
    const __half* hb = &g_Ah[(size_t)b * 196 * 1024 + h0];
    float4 acc = make_float4(0.f, 0.f, 0.f, 0.f);
#pragma unroll 4
    for (int p = 0; p < 196; p++) {
        uint2 u = *(const uint2*)(hb + (size_t)p * 1024);
        float2 lo = __half22float2(*(__half2*)&u.x);
        float2 hi = __half22float2(*(__half2*)&u.y);
        float wp = ws[p];
        acc.x += lo.x * wp; acc.y += lo.y * wp;
        acc.z += hi.x * wp; acc.w += hi.y * wp;
    }
    const int idx = b * 1024 + h0;
    float4 sa = *(const float4*)&g_sent_aff[idx];
    float4 ha = *(const float4*)&g_hid_aff[idx];
    float wl = ws[196];
    acc.x += sa.x * wl + ha.x; acc.y += sa.y * wl + ha.y;
    acc.z += sa.z * wl + ha.z; acc.w += sa.w * wl + ha.w;
    *(float4*)&g_ctx[idx] = acc;
}

// ------------------------------------------------------------------
extern "C" void kernel_launch(void* const* d_in, const int* in_sizes, int n_in,
                              void* d_out, int out_size)
{
    (void)in_sizes; (void)n_in; (void)out_size;
    const float* spatial   = (const float*)d_in[0];
    const float* decoder   = (const float*)d_in[1];
    const float* st        = (const float*)d_in[2];
    const float* W_sen_aff = (const float*)d_in[3];
    const float* b_sen_aff = (const float*)d_in[4];
    const float* W_sen_att = (const float*)d_in[5];
    const float* b_sen_att = (const float*)d_in[6];
    const float* W_h_aff   = (const float*)d_in[7];
    const float* b_h_aff   = (const float*)d_in[8];
    const float* W_h_att   = (const float*)d_in[9];
    const float* b_h_att   = (const float*)d_in[10];
    const float* W_v_att   = (const float*)d_in[11];
    const float* b_v_att   = (const float*)d_in[12];
    const float* W_alpha   = (const float*)d_in[13];
    // d_in[14] = b_alpha: softmax-invariant constant, dropped
    const float* W_ctx     = (const float*)d_in[15];
    const float* b_ctx     = (const float*)d_in[16];

    float* out      = (float*)d_out;
    float* out_l    = out;
    float* out_w    = out + Bz * Hz;
    float* out_beta = out + Bz * Hz + Bz * 197;

    float *sa, *ha, *st_att, *h_att, *ctx, *affp, *attp, *finp;
    cudaGetSymbolAddress((void**)&sa,     g_sent_aff);
    cudaGetSymbolAddress((void**)&ha,     g_hid_aff);
    cudaGetSymbolAddress((void**)&st_att, g_sent_att);
    cudaGetSymbolAddress((void**)&h_att,  g_hid_att);
    cudaGetSymbolAddress((void**)&ctx,    g_ctx);
    cudaGetSymbolAddress((void**)&affp,   g_aff_part);
    cudaGetSymbolAddress((void**)&attp,   g_att_part);
    cudaGetSymbolAddress((void**)&finp,   g_fin_part);

    const size_t aff_slabs = (size_t)8 * 256 * Hz;
    const size_t att_slabs = (size_t)8 * 256 * Az;
    float* affp_hid  = affp;
    float* affp_sent = affp + aff_slabs;
    float* attp_hid  = attp;
    float* attp_sent = attp + att_slabs;

    const int BIG_SMEM = NSTAGE * STG_BYTES;   // 56832
    cudaFuncSetAttribute(big_attn_mma,
                         cudaFuncAttributeMaxDynamicSharedMemorySize, BIG_SMEM);

    static cudaStream_t s2 = nullptr, s3 = nullptr;
    static cudaEvent_t ev_fork = nullptr, ev_conv = nullptr, ev_sent = nullptr;
    if (!s2) {
        cudaStreamCreateWithFlags(&s2, cudaStreamNonBlocking);
        cudaStreamCreateWithFlags(&s3, cudaStreamNonBlocking);
        cudaEventCreateWithFlags(&ev_fork, cudaEventDisableTiming);
        cudaEventCreateWithFlags(&ev_conv, cudaEventDisableTiming);
        cudaEventCreateWithFlags(&ev_sent, cudaEventDisableTiming);
    }

    // ---- fork ----
    cudaEventRecord(ev_fork, 0);
    cudaStreamWaitEvent(s2, ev_fork, 0);
    cudaStreamWaitEvent(s3, ev_fork, 0);

    // s2: conversions (run concurrently with the hidden chain on main)
    convB_kernel<<<256, 256, 0, s2>>>(W_v_att);
    convA_kernel<<<25088, 256, 0, s2>>>(spatial);
    cudaEventRecord(ev_conv, s2);

    // s3: sentinel chain (needed only by softmax_context)
    gemm_splitk<<<dim3(16, 4, 8), 256, 0, s3>>>(st, W_sen_aff, affp_sent, Hz);
    combine1<<<256, 256, 0, s3>>>(affp_sent, b_sen_aff, sa, Hz, 1);
    gemm_splitk<<<dim3(8, 4, 8), 256, 0, s3>>>(sa, W_sen_att, attp_sent, Az);
    combine1<<<128, 256, 0, s3>>>(attp_sent, b_sen_att, st_att, Az, 0);
    cudaEventRecord(ev_sent, s3);

    // main: hidden chain (gates the big GEMM)
    gemm_splitk<<<dim3(16, 4, 8), 256>>>(decoder, W_h_aff, affp_hid, Hz);
    combine1<<<256, 256>>>(affp_hid, b_h_aff, ha, Hz, 2);
    gemm_splitk<<<dim3(8, 4, 8), 256>>>(ha, W_h_att, attp_hid, Az);
    combine1<<<128, 256>>>(attp_hid, b_h_att, h_att, Az, 0);

    // big GEMM: single launch (one ramp + one drain)
    cudaStreamWaitEvent(0, ev_conv, 0);
    big_attn_mma<<<dim3(4, 392), 256, BIG_SMEM>>>(b_v_att, W_alpha);

    // softmax + context (needs sentinel chain + alpha + g_Ah)
    cudaStreamWaitEvent(0, ev_sent, 0);
    softmax_context_kernel<<<Bz, 256>>>(W_alpha, out_w, out_beta);

    // out_l = tanh(ctx @ W_ctx + b_ctx)
    gemm_splitk<<<dim3(16, 4, 8), 256>>>(ctx, W_ctx, finp, Hz);
    combine1<<<256, 256>>>(finp, b_ctx, out_l, Hz, 2);
}